// round 13
// baseline (speedup 1.0000x reference)
#include <cuda_runtime.h>
#include <math.h>

// Problem constants
#define BB    4
#define CC    768
#define LL    8192
#define NFFT  16384
#define EMB   33
#define ORD   64
#define NT    1024

#define C1f 0.923879532511287f   // cos(pi/8)
#define S1f 0.382683432365090f   // sin(pi/8)
#define R2f 0.707106781186548f   // sqrt(2)/2

// Round-7 skew (measured bank-optimal): groups of 16 float2 contiguous, 16B-aligned
#define SK(i) ((i) + (((i) >> 4) << 1))
#define DATA_SZ 18432                         // SK(16383)=18429
#define TW_SZ   1088                          // 1024 + 64
#define FFT_SMEM ((DATA_SZ + TW_SZ) * (int)sizeof(float2))

// Fused filter kernel dynamic smem layout (floats)
#define FS_W0    0                            // [33*64]  = 2112
#define FS_W12   2112                         // [8192]   W1|W2, reused for Wout chunk
#define FS_H     10304                        // [32*68]  = 2176
#define FS_TOTAL 12480
#define FILT_SMEM (FS_TOTAL * (int)sizeof(float))

// Static device scratch (allocation-free rule)
__device__ float  g_k [CC * LL];
__device__ float2 g_KF[CC * NFFT];            // permuted spectrum / NFFT (layout: 64g+16r+slot)

__device__ __forceinline__ float2 cadd(float2 a, float2 b){ return make_float2(a.x+b.x, a.y+b.y); }
__device__ __forceinline__ float2 csub(float2 a, float2 b){ return make_float2(a.x-b.x, a.y-b.y); }
__device__ __forceinline__ float2 cmul(float2 a, float2 b){
    return make_float2(a.x*b.x - a.y*b.y, a.x*b.y + a.y*b.x);
}
__device__ __forceinline__ float2 cmulc(float2 a, float cr, float ci){
    return make_float2(a.x*cr - a.y*ci, a.x*ci + a.y*cr);
}
__device__ __forceinline__ float2 mni(float2 a){ return make_float2(a.y, -a.x); }   // a * -i
__device__ __forceinline__ float2 mpi(float2 a){ return make_float2(-a.y, a.x); }   // a * +i

__device__ __forceinline__ float2 shxor(float2 v, int mask){
    float2 r;
    r.x = __shfl_xor_sync(0xffffffffu, v.x, mask);
    r.y = __shfl_xor_sync(0xffffffffu, v.y, mask);
    return r;
}

// 128-thread named barrier; ids 1..8 (id 0 reserved for __syncthreads).
__device__ __forceinline__ void bar128(int tid){
    asm volatile("bar.sync %0, 128;" :: "r"(1 + (tid >> 7)) : "memory");
}

// After dft16/idft16, output index m lives at register slot OUTI(m) (involution)
#define OUTI(m) ((((m) & 3) << 2) | ((m) >> 2))

// Twiddle tables: q=1024 @0 (w=e^{-2pi i j/16384}), q=64 @1024
__device__ __forceinline__ void fill_tw(float2* tw, int tid) {
    float sn, cs;
    if (tid < 1024) {
        sincospif((float)tid * (1.0f/8192.0f), &sn, &cs);
        tw[tid] = make_float2(cs, -sn);
    }
    if (tid < 64) {
        sincospif((float)tid * (1.0f/512.0f), &sn, &cs);
        tw[1024 + tid] = make_float2(cs, -sn);
    }
}

// ---- DFT16 pieces (n=4c+d, m=r+4s; X_m -> v[4r+s]) ----
__device__ __forceinline__ void dft16_tail(float2 v[16]) {
    v[5]  = cmulc(v[5],  C1f, -S1f);
    v[6]  = cmulc(v[6],  R2f, -R2f);
    v[7]  = cmulc(v[7],  S1f, -C1f);
    v[9]  = cmulc(v[9],  R2f, -R2f);
    v[10] = mni(v[10]);
    v[11] = cmulc(v[11], -R2f, -R2f);
    v[13] = cmulc(v[13], S1f, -C1f);
    v[14] = cmulc(v[14], -R2f, -R2f);
    v[15] = cmulc(v[15], -C1f, S1f);
    #pragma unroll
    for (int r = 0; r < 4; ++r) {
        float2 a = v[4*r], b = v[4*r+1], c = v[4*r+2], e = v[4*r+3];
        float2 u0 = cadd(a,c), u1 = csub(a,c), u2 = cadd(b,e), u3 = csub(b,e);
        v[4*r]   = cadd(u0,u2);
        v[4*r+1] = cadd(u1, mni(u3));
        v[4*r+2] = csub(u0,u2);
        v[4*r+3] = cadd(u1, mpi(u3));
    }
}
__device__ __forceinline__ void dft16(float2 v[16]) {
    #pragma unroll
    for (int dd = 0; dd < 4; ++dd) {
        float2 a = v[dd], b = v[4+dd], c = v[8+dd], e = v[12+dd];
        float2 t0 = cadd(a,c), t1 = csub(a,c), t2 = cadd(b,e), t3 = csub(b,e);
        v[dd]    = cadd(t0,t2);
        v[4+dd]  = cadd(t1, mni(t3));
        v[8+dd]  = csub(t0,t2);
        v[12+dd] = cadd(t1, mpi(t3));
    }
    dft16_tail(v);
}
__device__ __forceinline__ void idft16_cols_tw(float2 v[16]) {
    #pragma unroll
    for (int dd = 0; dd < 4; ++dd) {
        float2 a = v[dd], b = v[4+dd], c = v[8+dd], e = v[12+dd];
        float2 t0 = cadd(a,c), t1 = csub(a,c), t2 = cadd(b,e), t3 = csub(b,e);
        v[dd]    = cadd(t0,t2);
        v[4+dd]  = cadd(t1, mpi(t3));
        v[8+dd]  = csub(t0,t2);
        v[12+dd] = cadd(t1, mni(t3));
    }
    v[5]  = cmulc(v[5],  C1f, S1f);
    v[6]  = cmulc(v[6],  R2f, R2f);
    v[7]  = cmulc(v[7],  S1f, C1f);
    v[9]  = cmulc(v[9],  R2f, R2f);
    v[10] = mpi(v[10]);
    v[11] = cmulc(v[11], -R2f, R2f);
    v[13] = cmulc(v[13], S1f, C1f);
    v[14] = cmulc(v[14], -R2f, R2f);
    v[15] = cmulc(v[15], -C1f, -S1f);
}
__device__ __forceinline__ void idft16(float2 v[16]) {
    idft16_cols_tw(v);
    #pragma unroll
    for (int r = 0; r < 4; ++r) {
        float2 a = v[4*r], b = v[4*r+1], c = v[4*r+2], e = v[4*r+3];
        float2 u0 = cadd(a,c), u1 = csub(a,c), u2 = cadd(b,e), u3 = csub(b,e);
        v[4*r]   = cadd(u0,u2);
        v[4*r+1] = cadd(u1, mpi(u3));
        v[4*r+2] = csub(u0,u2);
        v[4*r+3] = cadd(u1, mni(u3));
    }
}

// ---- multiply v[m] *= w^m, m=1..15, via 4 parallel chains (depth<=4) ----
__device__ __forceinline__ void twpow_mul(float2 v[16], float2 w) {
    float2 W2 = cmul(w, w), W3 = cmul(W2, w), W4 = cmul(W2, W2);
    float2 a = w, b = W2, c = W3, e = W4;
    v[1]  = cmul(v[1],  a);  v[2]  = cmul(v[2],  b);
    v[3]  = cmul(v[3],  c);  v[4]  = cmul(v[4],  e);
    a = cmul(a, W4); b = cmul(b, W4); c = cmul(c, W4); e = cmul(e, W4);
    v[5]  = cmul(v[5],  a);  v[6]  = cmul(v[6],  b);
    v[7]  = cmul(v[7],  c);  v[8]  = cmul(v[8],  e);
    a = cmul(a, W4); b = cmul(b, W4); c = cmul(c, W4); e = cmul(e, W4);
    v[9]  = cmul(v[9],  a);  v[10] = cmul(v[10], b);
    v[11] = cmul(v[11], c);  v[12] = cmul(v[12], e);
    a = cmul(a, W4); b = cmul(b, W4); c = cmul(c, W4);
    v[13] = cmul(v[13], a);  v[14] = cmul(v[14], b);  v[15] = cmul(v[15], c);
}

// ---- Store butterfly outputs with twiddle powers via 4 parallel chains ----
__device__ __forceinline__ void store_tw16(float2* d, int base, int sh,
                                           const float2 v[16], float2 w) {
    d[SK(base)] = v[0];
    float2 W2 = cmul(w, w), W3 = cmul(W2, w), W4 = cmul(W2, W2);
    float2 a = w, b = W2, c = W3, e = W4;
    d[SK(base + (1 << sh))]  = cmul(v[OUTI(1)],  a);
    d[SK(base + (2 << sh))]  = cmul(v[OUTI(2)],  b);
    d[SK(base + (3 << sh))]  = cmul(v[OUTI(3)],  c);
    d[SK(base + (4 << sh))]  = cmul(v[OUTI(4)],  e);
    a = cmul(a, W4); b = cmul(b, W4); c = cmul(c, W4); e = cmul(e, W4);
    d[SK(base + (5 << sh))]  = cmul(v[OUTI(5)],  a);
    d[SK(base + (6 << sh))]  = cmul(v[OUTI(6)],  b);
    d[SK(base + (7 << sh))]  = cmul(v[OUTI(7)],  c);
    d[SK(base + (8 << sh))]  = cmul(v[OUTI(8)],  e);
    a = cmul(a, W4); b = cmul(b, W4); c = cmul(c, W4); e = cmul(e, W4);
    d[SK(base + (9 << sh))]  = cmul(v[OUTI(9)],  a);
    d[SK(base + (10 << sh))] = cmul(v[OUTI(10)], b);
    d[SK(base + (11 << sh))] = cmul(v[OUTI(11)], c);
    d[SK(base + (12 << sh))] = cmul(v[OUTI(12)], e);
    a = cmul(a, W4); b = cmul(b, W4); c = cmul(c, W4);
    d[SK(base + (13 << sh))] = cmul(v[OUTI(13)], a);
    d[SK(base + (14 << sh))] = cmul(v[OUTI(14)], b);
    d[SK(base + (15 << sh))] = cmul(v[OUTI(15)], c);
}

// ---- Load + multiply by conj twiddle powers ----
__device__ __forceinline__ void load_tw16(const float2* d, int base, int sh,
                                          float2 v[16], float2 w) {
    #pragma unroll
    for (int m = 0; m < 16; ++m) v[m] = d[SK(base + (m << sh))];
    twpow_mul(v, w);
}

// ---- Stage F0: radix-16, q=1024, reads two zero-padded real rows from gmem ----
__device__ __forceinline__ void f0_fwd(float2* d, const float2* tw,
                                       const float* __restrict__ r0,
                                       const float* __restrict__ r1, int tid) {
    int j = tid;
    float2 v[16];
    #pragma unroll
    for (int dd = 0; dd < 4; ++dd) {
        int ia = j + (dd << 10);
        int ib = j + ((dd + 4) << 10);
        float2 a = make_float2(r0[ia], r1[ia]);
        float2 b = make_float2(r0[ib], r1[ib]);
        v[dd]    = cadd(a, b);
        v[4+dd]  = cadd(a, mni(b));
        v[8+dd]  = csub(a, b);
        v[12+dd] = cadd(a, mpi(b));
    }
    dft16_tail(v);
    store_tw16(d, j, 10, v, tw[j]);
    __syncthreads();
}

// ---- Middle radix-16 stage, q=64 (no trailing barrier) ----
__device__ __forceinline__ void r16_fwd64(float2* d, const float2* tw, int tid) {
    int j = tid & 63;
    int base = ((tid >> 6) << 10) | j;
    float2 v[16];
    #pragma unroll
    for (int m = 0; m < 16; ++m) v[m] = d[SK(base + (m << 6))];
    dft16(v);
    store_tw16(d, base, 6, v, tw[1024 + j]);
}
__device__ __forceinline__ void r16_inv64(float2* d, const float2* tw, int tid) {
    int j = tid & 63;
    int base = ((tid >> 6) << 10) | j;
    float2 w = tw[1024 + j]; w.y = -w.y;
    float2 v[16];
    load_tw16(d, base, 6, v, w);
    idft16(v);
    #pragma unroll
    for (int m = 0; m < 16; ++m) d[SK(base + (m << 6))] = v[OUTI(m)];
}

// ---- Shuffle-based 64-pt forward DFT over thread's 16 consecutive elements ----
__device__ __forceinline__ void fwd64_regs(float2 v[16], int t, float2 wr) {
    float f2 = (t & 2) ? -1.0f : 1.0f;
    float f1 = (t & 1) ? -1.0f : 1.0f;
    bool t3 = (t == 3);
    #pragma unroll
    for (int m = 0; m < 16; ++m) {
        float2 p = shxor(v[m], 2);
        v[m] = make_float2(f2 * v[m].x + p.x, f2 * v[m].y + p.y);
        if (t3) v[m] = mni(v[m]);
        p = shxor(v[m], 1);
        v[m] = make_float2(f1 * v[m].x + p.x, f1 * v[m].y + p.y);
    }
    twpow_mul(v, wr);     // w64^(r*m)
    dft16(v);
}

// ---- Shuffle-based 64-pt inverse ----
__device__ __forceinline__ void inv64_regs(float2 v[16], int t, float2 wrc) {
    float2 w2[16];
    #pragma unroll
    for (int k = 0; k < 16; ++k) w2[k] = v[OUTI(k)];   // natural freq order
    idft16(w2);                                         // time m at slot OUTI(m)
    #pragma unroll
    for (int m = 0; m < 16; ++m) v[m] = w2[OUTI(m)];    // natural time order
    twpow_mul(v, wrc);    // conj(w64)^(r*m)
    float f2 = (t & 2) ? -1.0f : 1.0f;
    float f1 = (t & 1) ? -1.0f : 1.0f;
    bool t3 = (t == 3);
    #pragma unroll
    for (int m = 0; m < 16; ++m) {
        float2 p = shxor(v[m], 1);
        v[m] = make_float2(f1 * v[m].x + p.x, f1 * v[m].y + p.y);
        if (t3) v[m] = mpi(v[m]);
        p = shxor(v[m], 2);
        v[m] = make_float2(f2 * v[m].x + p.x, f2 * v[m].y + p.y);
    }
}

// ---- conv middle: fwd64 + pointwise Kf + inv64 entirely in registers ----
__device__ __forceinline__ void conv_mid(float2* d, const float2* __restrict__ kf, int tid) {
    int t = tid & 3;
    int r = ((t & 1) << 1) | (t >> 1);
    float sn, cs;
    sincospif((float)r * (1.0f/32.0f), &sn, &cs);
    int base = tid << 4;
    float4* p4 = (float4*)(d + SK(base));
    float2 v[16];
    #pragma unroll
    for (int u = 0; u < 8; ++u) {
        float4 q = p4[u];
        v[2*u]   = make_float2(q.x, q.y);
        v[2*u+1] = make_float2(q.z, q.w);
    }
    fwd64_regs(v, t, make_float2(cs, -sn));
    const float4* k4 = (const float4*)(kf + (((tid >> 2) << 6) + (r << 4)));
    #pragma unroll
    for (int u = 0; u < 8; ++u) {
        float4 kk = k4[u];
        v[2*u]   = cmul(v[2*u],   make_float2(kk.x, kk.y));
        v[2*u+1] = cmul(v[2*u+1], make_float2(kk.z, kk.w));
    }
    inv64_regs(v, t, make_float2(cs, sn));
    #pragma unroll
    for (int u = 0; u < 8; ++u)
        p4[u] = make_float4(v[2*u].x, v[2*u].y, v[2*u+1].x, v[2*u+1].y);
}

// ---- kf middle: fwd64 in registers, store at permuted base (g, r, slot) ----
__device__ __forceinline__ void kf_mid(float2* d, int tid) {
    int t = tid & 3;
    int r = ((t & 1) << 1) | (t >> 1);
    float sn, cs;
    sincospif((float)r * (1.0f/32.0f), &sn, &cs);
    const float4* p4 = (const float4*)(d + SK(tid << 4));
    float2 v[16];
    #pragma unroll
    for (int u = 0; u < 8; ++u) {
        float4 q = p4[u];
        v[2*u]   = make_float2(q.x, q.y);
        v[2*u+1] = make_float2(q.z, q.w);
    }
    fwd64_regs(v, t, make_float2(cs, -sn));
    int sbase = ((tid >> 2) << 6) + (r << 4);
    float4* s4 = (float4*)(d + SK(sbase));
    #pragma unroll
    for (int u = 0; u < 8; ++u)
        s4[u] = make_float4(v[2*u].x, v[2*u].y, v[2*u+1].x, v[2*u+1].y);
}

// ---- Stage I3: inverse radix-16 q=1024, only outputs m<8, write gmem + bias ----
__device__ __forceinline__ void i3_store(const float2* d, const float2* tw,
                                         const float* __restrict__ x0,
                                         const float* __restrict__ x1,
                                         float* __restrict__ o0,
                                         float* __restrict__ o1,
                                         float bc, int tid) {
    int j = tid;
    float2 w = tw[j]; w.y = -w.y;
    float2 v[16];
    load_tw16(d, j, 10, v, w);
    idft16_cols_tw(v);
    #pragma unroll
    for (int r = 0; r < 4; ++r) {
        float2 a = v[4*r], b = v[4*r+1], c = v[4*r+2], e = v[4*r+3];
        float2 u0 = cadd(a,c), u1 = csub(a,c), u2 = cadd(b,e), u3 = csub(b,e);
        float2 y0 = cadd(u0,u2);
        float2 y1 = cadd(u1, mpi(u3));
        int i0 = j + (r << 10);
        int i1 = j + ((r + 4) << 10);
        o0[i0] = y0.x + x0[i0] * bc;  o1[i0] = y0.y + x1[i0] * bc;
        o0[i1] = y1.x + x0[i1] * bc;  o1[i1] = y1.y + x1[i1] * bc;
    }
}

// ---------------- Kernel 1: FUSED implicit MLP + projection + modulation ----------
// grid (LL/32, 2). Phase 1: warp-local MLP (one warp per position, lane owns 2
// hidden units, shuffle broadcast; EMB=33 -> e=32 term handled via a broadcast
// gmem load, NOT shuffle — a warp has only 32 lanes). Phase 2: project onto the
// 384 channels owned by blockIdx.y (3 chunks of 128).
__global__ void __launch_bounds__(256) filt_kernel(const float* __restrict__ z,
                                                   const float* __restrict__ W0, const float* __restrict__ b0,
                                                   const float* __restrict__ W1, const float* __restrict__ b1,
                                                   const float* __restrict__ W2, const float* __restrict__ b2,
                                                   const float* __restrict__ freq,
                                                   const float* __restrict__ Wout,
                                                   const float* __restrict__ deltas) {
    extern __shared__ float fs[];
    float* sW0  = fs + FS_W0;     // [33*64]
    float* sW12 = fs + FS_W12;    // [8192] W1|W2, reused for Wout chunks in phase 2
    float* sH   = fs + FS_H;      // [32][68]

    int tid  = threadIdx.x;
    int lane = tid & 31;
    int wrp  = tid >> 5;
    int lt   = blockIdx.x * 32;

    for (int i = tid; i < EMB * ORD; i += 256) sW0[i] = W0[i];
    for (int i = tid; i < ORD * ORD; i += 256) sW12[i] = W1[i];
    for (int i = tid; i < ORD * ORD; i += 256) sW12[4096 + i] = W2[i];
    // per-lane params for outputs o = 2*lane, 2*lane+1
    float fq0 = freq[2*lane],  fq1 = freq[2*lane + 1];
    float b0a = b0[2*lane],    b0b = b0[2*lane + 1];
    float b1a = b1[2*lane],    b1b = b1[2*lane + 1];
    float b2a = b2[2*lane],    b2b = b2[2*lane + 1];
    __syncthreads();

    // ---- Phase 1: warp-local MLP, 4 positions per warp ----
    const float2* W0f2 = (const float2*)sW0;            // [33][32]
    const float2* W1f2 = (const float2*)sW12;           // [64][32]
    const float2* W2f2 = (const float2*)(sW12 + 4096);  // [64][32]
    for (int k = 0; k < 4; ++k) {
        int pos = wrp * 4 + k;
        int l = lt + pos;
        float zv    = z[l * EMB + lane];       // elements 0..31
        float zlast = z[l * EMB + 32];         // element 32 (broadcast load)
        float acc0 = b0a, acc1 = b0b;
        #pragma unroll
        for (int e = 0; e < 32; ++e) {
            float ze = __shfl_sync(0xffffffffu, zv, e);
            float2 ww = W0f2[e * 32 + lane];
            acc0 += ze * ww.x;  acc1 += ze * ww.y;
        }
        {
            float2 ww = W0f2[32 * 32 + lane];
            acc0 += zlast * ww.x;  acc1 += zlast * ww.y;
        }
        float h0 = sinf(fq0 * acc0), h1 = sinf(fq1 * acc1);

        acc0 = b1a; acc1 = b1b;
        #pragma unroll 8
        for (int i = 0; i < 32; ++i) {
            float g0 = __shfl_sync(0xffffffffu, h0, i);
            float g1 = __shfl_sync(0xffffffffu, h1, i);
            float2 wa = W1f2[(2*i)     * 32 + lane];
            float2 wb = W1f2[(2*i + 1) * 32 + lane];
            acc0 += g0 * wa.x + g1 * wb.x;
            acc1 += g0 * wa.y + g1 * wb.y;
        }
        h0 = sinf(fq0 * acc0);  h1 = sinf(fq1 * acc1);

        acc0 = b2a; acc1 = b2b;
        #pragma unroll 8
        for (int i = 0; i < 32; ++i) {
            float g0 = __shfl_sync(0xffffffffu, h0, i);
            float g1 = __shfl_sync(0xffffffffu, h1, i);
            float2 wa = W2f2[(2*i)     * 32 + lane];
            float2 wb = W2f2[(2*i + 1) * 32 + lane];
            acc0 += g0 * wa.x + g1 * wb.x;
            acc1 += g0 * wa.y + g1 * wb.y;
        }
        h0 = sinf(fq0 * acc0);  h1 = sinf(fq1 * acc1);

        // store to sH[pos][2*lane .. 2*lane+1]  (row stride 68 floats, 8B aligned)
        ((float2*)(sH + pos * 68))[lane] = make_float2(h0, h1);
    }
    __syncthreads();

    // ---- Phase 2: projection to 384 channels (3 chunks of 128) + modulation ----
    int ll = tid & 31;
    int cq = tid >> 5;
    int cb = blockIdx.y * 384;
    float hreg[ORD];
    {
        const float4* row = (const float4*)(sH + ll * 68);
        #pragma unroll
        for (int i = 0; i < 16; ++i) {
            float4 t = row[i];
            hreg[4*i] = t.x; hreg[4*i+1] = t.y; hreg[4*i+2] = t.z; hreg[4*i+3] = t.w;
        }
    }
    float tl = (float)(lt + ll) * (1.0f / (float)(LL - 1));
    float4* sW4 = (float4*)sW12;   // reuse weight region for Wout chunk [64][128]

    for (int ch = 0; ch < 3; ++ch) {
        int c0 = cb + ch * 128;
        __syncthreads();
        for (int idx = tid; idx < ORD * 128; idx += 256) {
            int oo = idx >> 7, cc = idx & 127;
            sW12[oo * 128 + cc] = Wout[oo * CC + c0 + cc];
        }
        __syncthreads();

        float acc[16];
        #pragma unroll
        for (int j = 0; j < 16; ++j) acc[j] = 0.0f;
        #pragma unroll 8
        for (int oo = 0; oo < ORD; ++oo) {
            float h = hreg[oo];
            const float4* row = sW4 + oo * 32 + cq * 4;
            #pragma unroll
            for (int j = 0; j < 4; ++j) {
                float4 w = row[j];
                acc[4*j+0] += h * w.x;
                acc[4*j+1] += h * w.y;
                acc[4*j+2] += h * w.z;
                acc[4*j+3] += h * w.w;
            }
        }
        #pragma unroll
        for (int j = 0; j < 16; ++j) {
            int c = c0 + cq * 16 + j;
            float m = expf(-tl * fabsf(deltas[c]));
            g_k[c * LL + lt + ll] = acc[j] * m;
        }
    }
}

// ---------------- Kernel 2: filter spectra, two channels per FFT ------------------
// Output layout per channel: p = 64g + 16r + u (u = dft16 slot; freq s = OUTI(u)).
__global__ void __launch_bounds__(NT, 1) kf_fft_kernel() {
    extern __shared__ float2 sm[];
    float2* data = sm;
    float2* tw   = sm + DATA_SZ;
    int tid = threadIdx.x;
    int c0  = blockIdx.x * 2;
    int c1  = c0 + 1;

    fill_tw(tw, tid);
    f0_fwd(data, tw, g_k + (size_t)c0 * LL, g_k + (size_t)c1 * LL, tid);
    r16_fwd64(data, tw, tid);
    bar128(tid);
    kf_mid(data, tid);
    __syncthreads();

    const float s = 0.5f / (float)NFFT;
    float2* KF0 = g_KF + (size_t)c0 * NFFT;
    float2* KF1 = g_KF + (size_t)c1 * NFFT;
    for (int p = tid; p < NFFT; p += NT) {
        int g = p >> 6, rr = (p >> 4) & 3, u = p & 15;
        int ss = OUTI(u);
        int j  = (g >> 4) + ((g & 15) << 4) + (((ss << 2) | rr) << 8);
        int jn = (NFFT - j) & (NFFT - 1);
        int a2 = jn & 15, b2 = (jn >> 4) & 15, k2 = jn >> 8;
        int r2 = k2 & 3, s2 = k2 >> 2;
        int u2 = OUTI(s2);
        int p2 = (((a2 << 4) | b2) << 6) | (r2 << 4) | u2;
        float2 z1 = data[SK(p)];
        float2 z2 = data[SK(p2)];
        KF0[p] = make_float2(s * (z1.x + z2.x), s * (z1.y - z2.y));
        KF1[p] = make_float2(s * (z1.y + z2.y), s * (z2.x - z1.x));
    }
}

// ---------------- Kernel 3: batched FFT convolution (2 batches as one complex) ----
__global__ void __launch_bounds__(NT, 1) conv_fft_kernel(const float* __restrict__ x,
                                                         const float* __restrict__ bias,
                                                         float* __restrict__ out) {
    extern __shared__ float2 sm[];
    float2* data = sm;
    float2* tw   = sm + DATA_SZ;
    int tid = threadIdx.x;
    int c = blockIdx.x;
    int p = blockIdx.y;

    const float* x0 = x + ((size_t)(2*p)   * CC + c) * LL;
    const float* x1 = x + ((size_t)(2*p+1) * CC + c) * LL;

    fill_tw(tw, tid);
    f0_fwd(data, tw, x0, x1, tid);          // block barrier inside

    r16_fwd64(data, tw, tid);
    bar128(tid);                            // 64-block exchange within tid>>6 group

    conv_mid(data, g_KF + (size_t)c * NFFT, tid);
    bar128(tid);

    r16_inv64(data, tw, tid);
    __syncthreads();                        // i3 reads across all threads

    float bc = bias[c];
    float* o0 = out + ((size_t)(2*p)   * CC + c) * LL;
    float* o1 = out + ((size_t)(2*p+1) * CC + c) * LL;
    i3_store(data, tw, x0, x1, o0, o1, bc, tid);
}

extern "C" void kernel_launch(void* const* d_in, const int* in_sizes, int n_in,
                              void* d_out, int out_size) {
    const float* x      = (const float*)d_in[0];
    const float* bias   = (const float*)d_in[1];
    const float* z      = (const float*)d_in[2];
    const float* deltas = (const float*)d_in[3];
    const float* W0     = (const float*)d_in[4];
    const float* b0     = (const float*)d_in[5];
    const float* W1     = (const float*)d_in[6];
    const float* b1     = (const float*)d_in[7];
    const float* W2     = (const float*)d_in[8];
    const float* b2     = (const float*)d_in[9];
    const float* freq   = (const float*)d_in[10];
    const float* Wout   = (const float*)d_in[11];
    float* out = (float*)d_out;

    cudaFuncSetAttribute(filt_kernel,     cudaFuncAttributeMaxDynamicSharedMemorySize, FILT_SMEM);
    cudaFuncSetAttribute(kf_fft_kernel,   cudaFuncAttributeMaxDynamicSharedMemorySize, FFT_SMEM);
    cudaFuncSetAttribute(conv_fft_kernel, cudaFuncAttributeMaxDynamicSharedMemorySize, FFT_SMEM);

    filt_kernel<<<dim3(LL / 32, 2), 256, FILT_SMEM>>>(z, W0, b0, W1, b1, W2, b2, freq, Wout, deltas);
    kf_fft_kernel<<<CC / 2, NT, FFT_SMEM>>>();
    conv_fft_kernel<<<dim3(CC, BB / 2), NT, FFT_SMEM>>>(x, bias, out);
}

// round 14
// speedup vs baseline: 1.0132x; 1.0132x over previous
#include <cuda_runtime.h>
#include <math.h>

// Problem constants
#define BB    4
#define CC    768
#define LL    8192
#define NFFT  16384
#define EMB   33
#define ORD   64
#define NT    1024

#define C1f 0.923879532511287f   // cos(pi/8)
#define S1f 0.382683432365090f   // sin(pi/8)
#define R2f 0.707106781186548f   // sqrt(2)/2

// Round-7 skew (measured bank-optimal): groups of 16 float2 contiguous, 16B-aligned
#define SK(i) ((i) + (((i) >> 4) << 1))
#define DATA_SZ 18432                         // SK(16383)=18429
#define TW_SZ   1088                          // 1024 + 64
#define FFT_SMEM ((DATA_SZ + TW_SZ) * (int)sizeof(float2))

// Fused filter kernel dynamic smem layout (floats) -- 16 positions per block
#define FS_W0    0                            // [33*64]  = 2112
#define FS_W12   2112                         // [8192]   W1|W2, reused for Wout chunk
#define FS_Z     10304                        // [4][36]  = 144
#define FS_H1    10448                        // [4][68]  = 272
#define FS_H2    10720                        // [4][68]  = 272
#define FS_H     10992                        // [16][68] = 1088
#define FS_TOTAL 12080
#define FILT_SMEM (FS_TOTAL * (int)sizeof(float))

// Static device scratch (allocation-free rule)
__device__ float  g_k [CC * LL];
__device__ float2 g_KF[CC * NFFT];            // permuted spectrum / NFFT (layout: 64g+16r+slot)

__device__ __forceinline__ float2 cadd(float2 a, float2 b){ return make_float2(a.x+b.x, a.y+b.y); }
__device__ __forceinline__ float2 csub(float2 a, float2 b){ return make_float2(a.x-b.x, a.y-b.y); }
__device__ __forceinline__ float2 cmul(float2 a, float2 b){
    return make_float2(a.x*b.x - a.y*b.y, a.x*b.y + a.y*b.x);
}
__device__ __forceinline__ float2 cmulc(float2 a, float cr, float ci){
    return make_float2(a.x*cr - a.y*ci, a.x*ci + a.y*cr);
}
__device__ __forceinline__ float2 mni(float2 a){ return make_float2(a.y, -a.x); }   // a * -i
__device__ __forceinline__ float2 mpi(float2 a){ return make_float2(-a.y, a.x); }   // a * +i

__device__ __forceinline__ float2 shxor(float2 v, int mask){
    float2 r;
    r.x = __shfl_xor_sync(0xffffffffu, v.x, mask);
    r.y = __shfl_xor_sync(0xffffffffu, v.y, mask);
    return r;
}

// 128-thread named barrier; ids 1..8 (id 0 reserved for __syncthreads).
__device__ __forceinline__ void bar128(int tid){
    asm volatile("bar.sync %0, 128;" :: "r"(1 + (tid >> 7)) : "memory");
}

// After dft16/idft16, output index m lives at register slot OUTI(m) (involution)
#define OUTI(m) ((((m) & 3) << 2) | ((m) >> 2))

// Twiddle tables: q=1024 @0 (w=e^{-2pi i j/16384}), q=64 @1024
__device__ __forceinline__ void fill_tw(float2* tw, int tid) {
    float sn, cs;
    if (tid < 1024) {
        sincospif((float)tid * (1.0f/8192.0f), &sn, &cs);
        tw[tid] = make_float2(cs, -sn);
    }
    if (tid < 64) {
        sincospif((float)tid * (1.0f/512.0f), &sn, &cs);
        tw[1024 + tid] = make_float2(cs, -sn);
    }
}

// ---- DFT16 pieces (n=4c+d, m=r+4s; X_m -> v[4r+s]) ----
__device__ __forceinline__ void dft16_tail(float2 v[16]) {
    v[5]  = cmulc(v[5],  C1f, -S1f);
    v[6]  = cmulc(v[6],  R2f, -R2f);
    v[7]  = cmulc(v[7],  S1f, -C1f);
    v[9]  = cmulc(v[9],  R2f, -R2f);
    v[10] = mni(v[10]);
    v[11] = cmulc(v[11], -R2f, -R2f);
    v[13] = cmulc(v[13], S1f, -C1f);
    v[14] = cmulc(v[14], -R2f, -R2f);
    v[15] = cmulc(v[15], -C1f, S1f);
    #pragma unroll
    for (int r = 0; r < 4; ++r) {
        float2 a = v[4*r], b = v[4*r+1], c = v[4*r+2], e = v[4*r+3];
        float2 u0 = cadd(a,c), u1 = csub(a,c), u2 = cadd(b,e), u3 = csub(b,e);
        v[4*r]   = cadd(u0,u2);
        v[4*r+1] = cadd(u1, mni(u3));
        v[4*r+2] = csub(u0,u2);
        v[4*r+3] = cadd(u1, mpi(u3));
    }
}
__device__ __forceinline__ void dft16(float2 v[16]) {
    #pragma unroll
    for (int dd = 0; dd < 4; ++dd) {
        float2 a = v[dd], b = v[4+dd], c = v[8+dd], e = v[12+dd];
        float2 t0 = cadd(a,c), t1 = csub(a,c), t2 = cadd(b,e), t3 = csub(b,e);
        v[dd]    = cadd(t0,t2);
        v[4+dd]  = cadd(t1, mni(t3));
        v[8+dd]  = csub(t0,t2);
        v[12+dd] = cadd(t1, mpi(t3));
    }
    dft16_tail(v);
}
__device__ __forceinline__ void idft16_cols_tw(float2 v[16]) {
    #pragma unroll
    for (int dd = 0; dd < 4; ++dd) {
        float2 a = v[dd], b = v[4+dd], c = v[8+dd], e = v[12+dd];
        float2 t0 = cadd(a,c), t1 = csub(a,c), t2 = cadd(b,e), t3 = csub(b,e);
        v[dd]    = cadd(t0,t2);
        v[4+dd]  = cadd(t1, mpi(t3));
        v[8+dd]  = csub(t0,t2);
        v[12+dd] = cadd(t1, mni(t3));
    }
    v[5]  = cmulc(v[5],  C1f, S1f);
    v[6]  = cmulc(v[6],  R2f, R2f);
    v[7]  = cmulc(v[7],  S1f, C1f);
    v[9]  = cmulc(v[9],  R2f, R2f);
    v[10] = mpi(v[10]);
    v[11] = cmulc(v[11], -R2f, R2f);
    v[13] = cmulc(v[13], S1f, C1f);
    v[14] = cmulc(v[14], -R2f, R2f);
    v[15] = cmulc(v[15], -C1f, -S1f);
}
__device__ __forceinline__ void idft16(float2 v[16]) {
    idft16_cols_tw(v);
    #pragma unroll
    for (int r = 0; r < 4; ++r) {
        float2 a = v[4*r], b = v[4*r+1], c = v[4*r+2], e = v[4*r+3];
        float2 u0 = cadd(a,c), u1 = csub(a,c), u2 = cadd(b,e), u3 = csub(b,e);
        v[4*r]   = cadd(u0,u2);
        v[4*r+1] = cadd(u1, mpi(u3));
        v[4*r+2] = csub(u0,u2);
        v[4*r+3] = cadd(u1, mni(u3));
    }
}

// ---- multiply v[m] *= w^m, m=1..15, via 4 parallel chains (depth<=4) ----
__device__ __forceinline__ void twpow_mul(float2 v[16], float2 w) {
    float2 W2 = cmul(w, w), W3 = cmul(W2, w), W4 = cmul(W2, W2);
    float2 a = w, b = W2, c = W3, e = W4;
    v[1]  = cmul(v[1],  a);  v[2]  = cmul(v[2],  b);
    v[3]  = cmul(v[3],  c);  v[4]  = cmul(v[4],  e);
    a = cmul(a, W4); b = cmul(b, W4); c = cmul(c, W4); e = cmul(e, W4);
    v[5]  = cmul(v[5],  a);  v[6]  = cmul(v[6],  b);
    v[7]  = cmul(v[7],  c);  v[8]  = cmul(v[8],  e);
    a = cmul(a, W4); b = cmul(b, W4); c = cmul(c, W4); e = cmul(e, W4);
    v[9]  = cmul(v[9],  a);  v[10] = cmul(v[10], b);
    v[11] = cmul(v[11], c);  v[12] = cmul(v[12], e);
    a = cmul(a, W4); b = cmul(b, W4); c = cmul(c, W4);
    v[13] = cmul(v[13], a);  v[14] = cmul(v[14], b);  v[15] = cmul(v[15], c);
}

// ---- Store butterfly outputs with twiddle powers via 4 parallel chains ----
__device__ __forceinline__ void store_tw16(float2* d, int base, int sh,
                                           const float2 v[16], float2 w) {
    d[SK(base)] = v[0];
    float2 W2 = cmul(w, w), W3 = cmul(W2, w), W4 = cmul(W2, W2);
    float2 a = w, b = W2, c = W3, e = W4;
    d[SK(base + (1 << sh))]  = cmul(v[OUTI(1)],  a);
    d[SK(base + (2 << sh))]  = cmul(v[OUTI(2)],  b);
    d[SK(base + (3 << sh))]  = cmul(v[OUTI(3)],  c);
    d[SK(base + (4 << sh))]  = cmul(v[OUTI(4)],  e);
    a = cmul(a, W4); b = cmul(b, W4); c = cmul(c, W4); e = cmul(e, W4);
    d[SK(base + (5 << sh))]  = cmul(v[OUTI(5)],  a);
    d[SK(base + (6 << sh))]  = cmul(v[OUTI(6)],  b);
    d[SK(base + (7 << sh))]  = cmul(v[OUTI(7)],  c);
    d[SK(base + (8 << sh))]  = cmul(v[OUTI(8)],  e);
    a = cmul(a, W4); b = cmul(b, W4); c = cmul(c, W4); e = cmul(e, W4);
    d[SK(base + (9 << sh))]  = cmul(v[OUTI(9)],  a);
    d[SK(base + (10 << sh))] = cmul(v[OUTI(10)], b);
    d[SK(base + (11 << sh))] = cmul(v[OUTI(11)], c);
    d[SK(base + (12 << sh))] = cmul(v[OUTI(12)], e);
    a = cmul(a, W4); b = cmul(b, W4); c = cmul(c, W4);
    d[SK(base + (13 << sh))] = cmul(v[OUTI(13)], a);
    d[SK(base + (14 << sh))] = cmul(v[OUTI(14)], b);
    d[SK(base + (15 << sh))] = cmul(v[OUTI(15)], c);
}

// ---- Load + multiply by conj twiddle powers ----
__device__ __forceinline__ void load_tw16(const float2* d, int base, int sh,
                                          float2 v[16], float2 w) {
    #pragma unroll
    for (int m = 0; m < 16; ++m) v[m] = d[SK(base + (m << sh))];
    twpow_mul(v, w);
}

// ---- Stage F0: radix-16, q=1024, reads two zero-padded real rows from gmem ----
__device__ __forceinline__ void f0_fwd(float2* d, const float2* tw,
                                       const float* __restrict__ r0,
                                       const float* __restrict__ r1, int tid) {
    int j = tid;
    float2 v[16];
    #pragma unroll
    for (int dd = 0; dd < 4; ++dd) {
        int ia = j + (dd << 10);
        int ib = j + ((dd + 4) << 10);
        float2 a = make_float2(r0[ia], r1[ia]);
        float2 b = make_float2(r0[ib], r1[ib]);
        v[dd]    = cadd(a, b);
        v[4+dd]  = cadd(a, mni(b));
        v[8+dd]  = csub(a, b);
        v[12+dd] = cadd(a, mpi(b));
    }
    dft16_tail(v);
    store_tw16(d, j, 10, v, tw[j]);
    __syncthreads();
}

// ---- Middle radix-16 stage, q=64 (no trailing barrier) ----
__device__ __forceinline__ void r16_fwd64(float2* d, const float2* tw, int tid) {
    int j = tid & 63;
    int base = ((tid >> 6) << 10) | j;
    float2 v[16];
    #pragma unroll
    for (int m = 0; m < 16; ++m) v[m] = d[SK(base + (m << 6))];
    dft16(v);
    store_tw16(d, base, 6, v, tw[1024 + j]);
}
__device__ __forceinline__ void r16_inv64(float2* d, const float2* tw, int tid) {
    int j = tid & 63;
    int base = ((tid >> 6) << 10) | j;
    float2 w = tw[1024 + j]; w.y = -w.y;
    float2 v[16];
    load_tw16(d, base, 6, v, w);
    idft16(v);
    #pragma unroll
    for (int m = 0; m < 16; ++m) d[SK(base + (m << 6))] = v[OUTI(m)];
}

// ---- Shuffle-based 64-pt forward DFT over thread's 16 consecutive elements ----
__device__ __forceinline__ void fwd64_regs(float2 v[16], int t, float2 wr) {
    float f2 = (t & 2) ? -1.0f : 1.0f;
    float f1 = (t & 1) ? -1.0f : 1.0f;
    bool t3 = (t == 3);
    #pragma unroll
    for (int m = 0; m < 16; ++m) {
        float2 p = shxor(v[m], 2);
        v[m] = make_float2(f2 * v[m].x + p.x, f2 * v[m].y + p.y);
        if (t3) v[m] = mni(v[m]);
        p = shxor(v[m], 1);
        v[m] = make_float2(f1 * v[m].x + p.x, f1 * v[m].y + p.y);
    }
    twpow_mul(v, wr);     // w64^(r*m)
    dft16(v);
}

// ---- Shuffle-based 64-pt inverse ----
__device__ __forceinline__ void inv64_regs(float2 v[16], int t, float2 wrc) {
    float2 w2[16];
    #pragma unroll
    for (int k = 0; k < 16; ++k) w2[k] = v[OUTI(k)];   // natural freq order
    idft16(w2);                                         // time m at slot OUTI(m)
    #pragma unroll
    for (int m = 0; m < 16; ++m) v[m] = w2[OUTI(m)];    // natural time order
    twpow_mul(v, wrc);    // conj(w64)^(r*m)
    float f2 = (t & 2) ? -1.0f : 1.0f;
    float f1 = (t & 1) ? -1.0f : 1.0f;
    bool t3 = (t == 3);
    #pragma unroll
    for (int m = 0; m < 16; ++m) {
        float2 p = shxor(v[m], 1);
        v[m] = make_float2(f1 * v[m].x + p.x, f1 * v[m].y + p.y);
        if (t3) v[m] = mpi(v[m]);
        p = shxor(v[m], 2);
        v[m] = make_float2(f2 * v[m].x + p.x, f2 * v[m].y + p.y);
    }
}

// ---- conv middle: fwd64 + pointwise Kf + inv64 entirely in registers ----
__device__ __forceinline__ void conv_mid(float2* d, const float2* __restrict__ kf, int tid) {
    int t = tid & 3;
    int r = ((t & 1) << 1) | (t >> 1);
    float sn, cs;
    sincospif((float)r * (1.0f/32.0f), &sn, &cs);
    int base = tid << 4;
    float4* p4 = (float4*)(d + SK(base));
    float2 v[16];
    #pragma unroll
    for (int u = 0; u < 8; ++u) {
        float4 q = p4[u];
        v[2*u]   = make_float2(q.x, q.y);
        v[2*u+1] = make_float2(q.z, q.w);
    }
    fwd64_regs(v, t, make_float2(cs, -sn));
    const float4* k4 = (const float4*)(kf + (((tid >> 2) << 6) + (r << 4)));
    #pragma unroll
    for (int u = 0; u < 8; ++u) {
        float4 kk = k4[u];
        v[2*u]   = cmul(v[2*u],   make_float2(kk.x, kk.y));
        v[2*u+1] = cmul(v[2*u+1], make_float2(kk.z, kk.w));
    }
    inv64_regs(v, t, make_float2(cs, sn));
    #pragma unroll
    for (int u = 0; u < 8; ++u)
        p4[u] = make_float4(v[2*u].x, v[2*u].y, v[2*u+1].x, v[2*u+1].y);
}

// ---- kf middle: fwd64 in registers, store at permuted base (g, r, slot) ----
__device__ __forceinline__ void kf_mid(float2* d, int tid) {
    int t = tid & 3;
    int r = ((t & 1) << 1) | (t >> 1);
    float sn, cs;
    sincospif((float)r * (1.0f/32.0f), &sn, &cs);
    const float4* p4 = (const float4*)(d + SK(tid << 4));
    float2 v[16];
    #pragma unroll
    for (int u = 0; u < 8; ++u) {
        float4 q = p4[u];
        v[2*u]   = make_float2(q.x, q.y);
        v[2*u+1] = make_float2(q.z, q.w);
    }
    fwd64_regs(v, t, make_float2(cs, -sn));
    int sbase = ((tid >> 2) << 6) + (r << 4);
    float4* s4 = (float4*)(d + SK(sbase));
    #pragma unroll
    for (int u = 0; u < 8; ++u)
        s4[u] = make_float4(v[2*u].x, v[2*u].y, v[2*u+1].x, v[2*u+1].y);
}

// ---- Stage I3: inverse radix-16 q=1024, only outputs m<8, write gmem + bias ----
__device__ __forceinline__ void i3_store(const float2* d, const float2* tw,
                                         const float* __restrict__ x0,
                                         const float* __restrict__ x1,
                                         float* __restrict__ o0,
                                         float* __restrict__ o1,
                                         float bc, int tid) {
    int j = tid;
    float2 w = tw[j]; w.y = -w.y;
    float2 v[16];
    load_tw16(d, j, 10, v, w);
    idft16_cols_tw(v);
    #pragma unroll
    for (int r = 0; r < 4; ++r) {
        float2 a = v[4*r], b = v[4*r+1], c = v[4*r+2], e = v[4*r+3];
        float2 u0 = cadd(a,c), u1 = csub(a,c), u2 = cadd(b,e), u3 = csub(b,e);
        float2 y0 = cadd(u0,u2);
        float2 y1 = cadd(u1, mpi(u3));
        int i0 = j + (r << 10);
        int i1 = j + ((r + 4) << 10);
        o0[i0] = y0.x + x0[i0] * bc;  o1[i0] = y0.y + x1[i0] * bc;
        o0[i1] = y1.x + x0[i1] * bc;  o1[i1] = y1.y + x1[i1] * bc;
    }
}

// ---------------- Kernel 1: FUSED implicit MLP + projection + modulation ----------
// One block = 16 sequence positions (grid 512 -> ~3.5 CTAs/SM). Phase 1: block MLP
// (4 positions/iter x 4 iters). Phase 2: project to all 768 channels (6 chunks of
// 128; each thread owns 8 channels per chunk for its position).
__global__ void __launch_bounds__(256) filt_kernel(const float* __restrict__ z,
                                                   const float* __restrict__ W0, const float* __restrict__ b0,
                                                   const float* __restrict__ W1, const float* __restrict__ b1,
                                                   const float* __restrict__ W2, const float* __restrict__ b2,
                                                   const float* __restrict__ freq,
                                                   const float* __restrict__ Wout,
                                                   const float* __restrict__ deltas) {
    extern __shared__ float fs[];
    float* sW0  = fs + FS_W0;     // [33*64]
    float* sW12 = fs + FS_W12;    // [8192] W1|W2, reused for Wout chunks in phase 2
    float* sz   = fs + FS_Z;      // [4][36]
    float* sh1  = fs + FS_H1;     // [4][68]
    float* sh2  = fs + FS_H2;     // [4][68]
    float* sH   = fs + FS_H;      // [16][68]

    int tid = threadIdx.x;
    int o = tid & 63;
    int p = tid >> 6;
    int lt = blockIdx.x * 16;

    for (int i = tid; i < EMB * ORD; i += 256) sW0[i] = W0[i];
    for (int i = tid; i < ORD * ORD; i += 256) sW12[i] = W1[i];
    for (int i = tid; i < ORD * ORD; i += 256) sW12[4096 + i] = W2[i];
    float fb0 = b0[o], fb1 = b1[o], fb2 = b2[o], fq = freq[o];
    __syncthreads();

    // ---- Phase 1: MLP for 16 positions (4 iterations x 4 positions) ----
    for (int it = 0; it < 4; ++it) {
        int l = lt + it * 4 + p;
        if (o < EMB) sz[p * 36 + o] = z[l * EMB + o];
        __syncthreads();
        float acc = fb0;
        #pragma unroll
        for (int e = 0; e < EMB; ++e) acc += sz[p * 36 + e] * sW0[e * ORD + o];
        sh1[p * 68 + o] = sinf(fq * acc);
        __syncthreads();
        acc = fb1;
        #pragma unroll 8
        for (int i = 0; i < ORD; ++i) acc += sh1[p * 68 + i] * sW12[i * ORD + o];
        sh2[p * 68 + o] = sinf(fq * acc);
        __syncthreads();
        acc = fb2;
        #pragma unroll 8
        for (int i = 0; i < ORD; ++i) acc += sh2[p * 68 + i] * sW12[4096 + i * ORD + o];
        sH[(it * 4 + p) * 68 + o] = sinf(fq * acc);
        __syncthreads();
    }

    // ---- Phase 2: projection to 768 channels + exponential modulation ----
    int ll = tid & 15;            // position within tile
    int cs = tid >> 4;            // 0..15, owns 8 consecutive channels per chunk
    float hreg[ORD];
    {
        const float4* row = (const float4*)(sH + ll * 68);
        #pragma unroll
        for (int i = 0; i < 16; ++i) {
            float4 t = row[i];
            hreg[4*i] = t.x; hreg[4*i+1] = t.y; hreg[4*i+2] = t.z; hreg[4*i+3] = t.w;
        }
    }
    float tl = (float)(lt + ll) * (1.0f / (float)(LL - 1));
    float4* sW4 = (float4*)sW12;   // reuse weight region for Wout chunk [64][128]

    for (int ch = 0; ch < 6; ++ch) {
        int c0 = ch * 128;
        __syncthreads();
        for (int idx = tid; idx < ORD * 128; idx += 256) {
            int oo = idx >> 7, cc = idx & 127;
            sW12[oo * 128 + cc] = Wout[oo * CC + c0 + cc];
        }
        __syncthreads();

        float acc[8];
        #pragma unroll
        for (int j = 0; j < 8; ++j) acc[j] = 0.0f;
        #pragma unroll 8
        for (int oo = 0; oo < ORD; ++oo) {
            float h = hreg[oo];
            const float4* row = sW4 + oo * 32 + cs * 2;
            #pragma unroll
            for (int j = 0; j < 2; ++j) {
                float4 w = row[j];
                acc[4*j+0] += h * w.x;
                acc[4*j+1] += h * w.y;
                acc[4*j+2] += h * w.z;
                acc[4*j+3] += h * w.w;
            }
        }
        #pragma unroll
        for (int j = 0; j < 8; ++j) {
            int c = c0 + cs * 8 + j;
            float m = expf(-tl * fabsf(deltas[c]));
            g_k[c * LL + lt + ll] = acc[j] * m;
        }
    }
}

// ---------------- Kernel 2: filter spectra, two channels per FFT ------------------
// Output layout per channel: p = 64g + 16r + u (u = dft16 slot; freq s = OUTI(u)).
__global__ void __launch_bounds__(NT, 1) kf_fft_kernel() {
    extern __shared__ float2 sm[];
    float2* data = sm;
    float2* tw   = sm + DATA_SZ;
    int tid = threadIdx.x;
    int c0  = blockIdx.x * 2;
    int c1  = c0 + 1;

    fill_tw(tw, tid);
    f0_fwd(data, tw, g_k + (size_t)c0 * LL, g_k + (size_t)c1 * LL, tid);
    r16_fwd64(data, tw, tid);
    bar128(tid);
    kf_mid(data, tid);
    __syncthreads();

    const float s = 0.5f / (float)NFFT;
    float2* KF0 = g_KF + (size_t)c0 * NFFT;
    float2* KF1 = g_KF + (size_t)c1 * NFFT;
    for (int p = tid; p < NFFT; p += NT) {
        int g = p >> 6, rr = (p >> 4) & 3, u = p & 15;
        int ss = OUTI(u);
        int j  = (g >> 4) + ((g & 15) << 4) + (((ss << 2) | rr) << 8);
        int jn = (NFFT - j) & (NFFT - 1);
        int a2 = jn & 15, b2 = (jn >> 4) & 15, k2 = jn >> 8;
        int r2 = k2 & 3, s2 = k2 >> 2;
        int u2 = OUTI(s2);
        int p2 = (((a2 << 4) | b2) << 6) | (r2 << 4) | u2;
        float2 z1 = data[SK(p)];
        float2 z2 = data[SK(p2)];
        KF0[p] = make_float2(s * (z1.x + z2.x), s * (z1.y - z2.y));
        KF1[p] = make_float2(s * (z1.y + z2.y), s * (z2.x - z1.x));
    }
}

// ---------------- Kernel 3: batched FFT convolution (2 batches as one complex) ----
__global__ void __launch_bounds__(NT, 1) conv_fft_kernel(const float* __restrict__ x,
                                                         const float* __restrict__ bias,
                                                         float* __restrict__ out) {
    extern __shared__ float2 sm[];
    float2* data = sm;
    float2* tw   = sm + DATA_SZ;
    int tid = threadIdx.x;
    int c = blockIdx.x;
    int p = blockIdx.y;

    const float* x0 = x + ((size_t)(2*p)   * CC + c) * LL;
    const float* x1 = x + ((size_t)(2*p+1) * CC + c) * LL;

    fill_tw(tw, tid);
    f0_fwd(data, tw, x0, x1, tid);          // block barrier inside

    r16_fwd64(data, tw, tid);
    bar128(tid);                            // 64-block exchange within tid>>6 group

    conv_mid(data, g_KF + (size_t)c * NFFT, tid);
    bar128(tid);

    r16_inv64(data, tw, tid);
    __syncthreads();                        // i3 reads across all threads

    float bc = bias[c];
    float* o0 = out + ((size_t)(2*p)   * CC + c) * LL;
    float* o1 = out + ((size_t)(2*p+1) * CC + c) * LL;
    i3_store(data, tw, x0, x1, o0, o1, bc, tid);
}

extern "C" void kernel_launch(void* const* d_in, const int* in_sizes, int n_in,
                              void* d_out, int out_size) {
    const float* x      = (const float*)d_in[0];
    const float* bias   = (const float*)d_in[1];
    const float* z      = (const float*)d_in[2];
    const float* deltas = (const float*)d_in[3];
    const float* W0     = (const float*)d_in[4];
    const float* b0     = (const float*)d_in[5];
    const float* W1     = (const float*)d_in[6];
    const float* b1     = (const float*)d_in[7];
    const float* W2     = (const float*)d_in[8];
    const float* b2     = (const float*)d_in[9];
    const float* freq   = (const float*)d_in[10];
    const float* Wout   = (const float*)d_in[11];
    float* out = (float*)d_out;

    cudaFuncSetAttribute(filt_kernel,     cudaFuncAttributeMaxDynamicSharedMemorySize, FILT_SMEM);
    cudaFuncSetAttribute(kf_fft_kernel,   cudaFuncAttributeMaxDynamicSharedMemorySize, FFT_SMEM);
    cudaFuncSetAttribute(conv_fft_kernel, cudaFuncAttributeMaxDynamicSharedMemorySize, FFT_SMEM);

    filt_kernel<<<LL / 16, 256, FILT_SMEM>>>(z, W0, b0, W1, b1, W2, b2, freq, Wout, deltas);
    kf_fft_kernel<<<CC / 2, NT, FFT_SMEM>>>();
    conv_fft_kernel<<<dim3(CC, BB / 2), NT, FFT_SMEM>>>(x, bias, out);
}

// round 15
// speedup vs baseline: 1.0379x; 1.0243x over previous
#include <cuda_runtime.h>
#include <math.h>

// Problem constants
#define BB    4
#define CC    768
#define LL    8192
#define NFFT  16384
#define EMB   33
#define ORD   64
#define NT    1024

#define C1f 0.923879532511287f   // cos(pi/8)
#define S1f 0.382683432365090f   // sin(pi/8)
#define R2f 0.707106781186548f   // sqrt(2)/2

// Round-7 skew (measured bank-optimal): groups of 16 float2 contiguous, 16B-aligned
#define SK(i) ((i) + (((i) >> 4) << 1))
#define DATA_SZ 18432                         // SK(16383)=18429
#define TW_SZ   1088                          // 1024 + 64
#define FFT_SMEM ((DATA_SZ + TW_SZ) * (int)sizeof(float2))

// Fused filter kernel dynamic smem layout (floats) -- 16 positions per block
#define FS_W0    0                            // [33*64]  = 2112
#define FS_W12   2112                         // [8192]   W1|W2, reused for Wout chunk
#define FS_Z     10304                        // [4][36]  = 144
#define FS_H1    10448                        // [4][68]  = 272
#define FS_H2    10720                        // [4][68]  = 272
#define FS_H     10992                        // [16][68] = 1088
#define FS_TOTAL 12080
#define FILT_SMEM (FS_TOTAL * (int)sizeof(float))

// Static device scratch (allocation-free rule)
__device__ float  g_k [CC * LL];
__device__ float2 g_KF[CC * NFFT];            // permuted spectrum / NFFT (layout: 64g+16r+slot)

__device__ __forceinline__ float2 cadd(float2 a, float2 b){ return make_float2(a.x+b.x, a.y+b.y); }
__device__ __forceinline__ float2 csub(float2 a, float2 b){ return make_float2(a.x-b.x, a.y-b.y); }
__device__ __forceinline__ float2 cmul(float2 a, float2 b){
    return make_float2(a.x*b.x - a.y*b.y, a.x*b.y + a.y*b.x);
}
__device__ __forceinline__ float2 cmulc(float2 a, float cr, float ci){
    return make_float2(a.x*cr - a.y*ci, a.x*ci + a.y*cr);
}
__device__ __forceinline__ float2 mni(float2 a){ return make_float2(a.y, -a.x); }   // a * -i
__device__ __forceinline__ float2 mpi(float2 a){ return make_float2(-a.y, a.x); }   // a * +i

__device__ __forceinline__ float2 shxor(float2 v, int mask){
    float2 r;
    r.x = __shfl_xor_sync(0xffffffffu, v.x, mask);
    r.y = __shfl_xor_sync(0xffffffffu, v.y, mask);
    return r;
}

// 128-thread named barrier; ids 1..8 (id 0 reserved for __syncthreads).
__device__ __forceinline__ void bar128(int tid){
    asm volatile("bar.sync %0, 128;" :: "r"(1 + (tid >> 7)) : "memory");
}

// After dft16/idft16, output index m lives at register slot OUTI(m) (involution)
#define OUTI(m) ((((m) & 3) << 2) | ((m) >> 2))

// Twiddle tables: q=1024 @0 (w=e^{-2pi i j/16384}), q=64 @1024
__device__ __forceinline__ void fill_tw(float2* tw, int tid) {
    float sn, cs;
    if (tid < 1024) {
        sincospif((float)tid * (1.0f/8192.0f), &sn, &cs);
        tw[tid] = make_float2(cs, -sn);
    }
    if (tid < 64) {
        sincospif((float)tid * (1.0f/512.0f), &sn, &cs);
        tw[1024 + tid] = make_float2(cs, -sn);
    }
}

// ---- DFT16 pieces (n=4c+d, m=r+4s; X_m -> v[4r+s]) ----
__device__ __forceinline__ void dft16_tail(float2 v[16]) {
    v[5]  = cmulc(v[5],  C1f, -S1f);
    v[6]  = cmulc(v[6],  R2f, -R2f);
    v[7]  = cmulc(v[7],  S1f, -C1f);
    v[9]  = cmulc(v[9],  R2f, -R2f);
    v[10] = mni(v[10]);
    v[11] = cmulc(v[11], -R2f, -R2f);
    v[13] = cmulc(v[13], S1f, -C1f);
    v[14] = cmulc(v[14], -R2f, -R2f);
    v[15] = cmulc(v[15], -C1f, S1f);
    #pragma unroll
    for (int r = 0; r < 4; ++r) {
        float2 a = v[4*r], b = v[4*r+1], c = v[4*r+2], e = v[4*r+3];
        float2 u0 = cadd(a,c), u1 = csub(a,c), u2 = cadd(b,e), u3 = csub(b,e);
        v[4*r]   = cadd(u0,u2);
        v[4*r+1] = cadd(u1, mni(u3));
        v[4*r+2] = csub(u0,u2);
        v[4*r+3] = cadd(u1, mpi(u3));
    }
}
__device__ __forceinline__ void dft16(float2 v[16]) {
    #pragma unroll
    for (int dd = 0; dd < 4; ++dd) {
        float2 a = v[dd], b = v[4+dd], c = v[8+dd], e = v[12+dd];
        float2 t0 = cadd(a,c), t1 = csub(a,c), t2 = cadd(b,e), t3 = csub(b,e);
        v[dd]    = cadd(t0,t2);
        v[4+dd]  = cadd(t1, mni(t3));
        v[8+dd]  = csub(t0,t2);
        v[12+dd] = cadd(t1, mpi(t3));
    }
    dft16_tail(v);
}
__device__ __forceinline__ void idft16_cols_tw(float2 v[16]) {
    #pragma unroll
    for (int dd = 0; dd < 4; ++dd) {
        float2 a = v[dd], b = v[4+dd], c = v[8+dd], e = v[12+dd];
        float2 t0 = cadd(a,c), t1 = csub(a,c), t2 = cadd(b,e), t3 = csub(b,e);
        v[dd]    = cadd(t0,t2);
        v[4+dd]  = cadd(t1, mpi(t3));
        v[8+dd]  = csub(t0,t2);
        v[12+dd] = cadd(t1, mni(t3));
    }
    v[5]  = cmulc(v[5],  C1f, S1f);
    v[6]  = cmulc(v[6],  R2f, R2f);
    v[7]  = cmulc(v[7],  S1f, C1f);
    v[9]  = cmulc(v[9],  R2f, R2f);
    v[10] = mpi(v[10]);
    v[11] = cmulc(v[11], -R2f, R2f);
    v[13] = cmulc(v[13], S1f, C1f);
    v[14] = cmulc(v[14], -R2f, R2f);
    v[15] = cmulc(v[15], -C1f, -S1f);
}
__device__ __forceinline__ void idft16(float2 v[16]) {
    idft16_cols_tw(v);
    #pragma unroll
    for (int r = 0; r < 4; ++r) {
        float2 a = v[4*r], b = v[4*r+1], c = v[4*r+2], e = v[4*r+3];
        float2 u0 = cadd(a,c), u1 = csub(a,c), u2 = cadd(b,e), u3 = csub(b,e);
        v[4*r]   = cadd(u0,u2);
        v[4*r+1] = cadd(u1, mpi(u3));
        v[4*r+2] = csub(u0,u2);
        v[4*r+3] = cadd(u1, mni(u3));
    }
}

// ---- multiply v[m] *= w^m, m=1..15, via 4 parallel chains (depth<=4) ----
__device__ __forceinline__ void twpow_mul(float2 v[16], float2 w) {
    float2 W2 = cmul(w, w), W3 = cmul(W2, w), W4 = cmul(W2, W2);
    float2 a = w, b = W2, c = W3, e = W4;
    v[1]  = cmul(v[1],  a);  v[2]  = cmul(v[2],  b);
    v[3]  = cmul(v[3],  c);  v[4]  = cmul(v[4],  e);
    a = cmul(a, W4); b = cmul(b, W4); c = cmul(c, W4); e = cmul(e, W4);
    v[5]  = cmul(v[5],  a);  v[6]  = cmul(v[6],  b);
    v[7]  = cmul(v[7],  c);  v[8]  = cmul(v[8],  e);
    a = cmul(a, W4); b = cmul(b, W4); c = cmul(c, W4); e = cmul(e, W4);
    v[9]  = cmul(v[9],  a);  v[10] = cmul(v[10], b);
    v[11] = cmul(v[11], c);  v[12] = cmul(v[12], e);
    a = cmul(a, W4); b = cmul(b, W4); c = cmul(c, W4);
    v[13] = cmul(v[13], a);  v[14] = cmul(v[14], b);  v[15] = cmul(v[15], c);
}

// ---- Store butterfly outputs with twiddle powers via 4 parallel chains ----
__device__ __forceinline__ void store_tw16(float2* d, int base, int sh,
                                           const float2 v[16], float2 w) {
    d[SK(base)] = v[0];
    float2 W2 = cmul(w, w), W3 = cmul(W2, w), W4 = cmul(W2, W2);
    float2 a = w, b = W2, c = W3, e = W4;
    d[SK(base + (1 << sh))]  = cmul(v[OUTI(1)],  a);
    d[SK(base + (2 << sh))]  = cmul(v[OUTI(2)],  b);
    d[SK(base + (3 << sh))]  = cmul(v[OUTI(3)],  c);
    d[SK(base + (4 << sh))]  = cmul(v[OUTI(4)],  e);
    a = cmul(a, W4); b = cmul(b, W4); c = cmul(c, W4); e = cmul(e, W4);
    d[SK(base + (5 << sh))]  = cmul(v[OUTI(5)],  a);
    d[SK(base + (6 << sh))]  = cmul(v[OUTI(6)],  b);
    d[SK(base + (7 << sh))]  = cmul(v[OUTI(7)],  c);
    d[SK(base + (8 << sh))]  = cmul(v[OUTI(8)],  e);
    a = cmul(a, W4); b = cmul(b, W4); c = cmul(c, W4); e = cmul(e, W4);
    d[SK(base + (9 << sh))]  = cmul(v[OUTI(9)],  a);
    d[SK(base + (10 << sh))] = cmul(v[OUTI(10)], b);
    d[SK(base + (11 << sh))] = cmul(v[OUTI(11)], c);
    d[SK(base + (12 << sh))] = cmul(v[OUTI(12)], e);
    a = cmul(a, W4); b = cmul(b, W4); c = cmul(c, W4);
    d[SK(base + (13 << sh))] = cmul(v[OUTI(13)], a);
    d[SK(base + (14 << sh))] = cmul(v[OUTI(14)], b);
    d[SK(base + (15 << sh))] = cmul(v[OUTI(15)], c);
}

// ---- Load + multiply by conj twiddle powers ----
__device__ __forceinline__ void load_tw16(const float2* d, int base, int sh,
                                          float2 v[16], float2 w) {
    #pragma unroll
    for (int m = 0; m < 16; ++m) v[m] = d[SK(base + (m << sh))];
    twpow_mul(v, w);
}

// ---- Stage F0: radix-16, q=1024, reads two zero-padded real rows from gmem ----
__device__ __forceinline__ void f0_fwd(float2* d, const float2* tw,
                                       const float* __restrict__ r0,
                                       const float* __restrict__ r1, int tid) {
    int j = tid;
    float2 v[16];
    #pragma unroll
    for (int dd = 0; dd < 4; ++dd) {
        int ia = j + (dd << 10);
        int ib = j + ((dd + 4) << 10);
        float2 a = make_float2(r0[ia], r1[ia]);
        float2 b = make_float2(r0[ib], r1[ib]);
        v[dd]    = cadd(a, b);
        v[4+dd]  = cadd(a, mni(b));
        v[8+dd]  = csub(a, b);
        v[12+dd] = cadd(a, mpi(b));
    }
    dft16_tail(v);
    store_tw16(d, j, 10, v, tw[j]);
    __syncthreads();
}

// ---- Middle radix-16 stage, q=64 (no trailing barrier) ----
__device__ __forceinline__ void r16_fwd64(float2* d, const float2* tw, int tid) {
    int j = tid & 63;
    int base = ((tid >> 6) << 10) | j;
    float2 v[16];
    #pragma unroll
    for (int m = 0; m < 16; ++m) v[m] = d[SK(base + (m << 6))];
    dft16(v);
    store_tw16(d, base, 6, v, tw[1024 + j]);
}
__device__ __forceinline__ void r16_inv64(float2* d, const float2* tw, int tid) {
    int j = tid & 63;
    int base = ((tid >> 6) << 10) | j;
    float2 w = tw[1024 + j]; w.y = -w.y;
    float2 v[16];
    load_tw16(d, base, 6, v, w);
    idft16(v);
    #pragma unroll
    for (int m = 0; m < 16; ++m) d[SK(base + (m << 6))] = v[OUTI(m)];
}

// ---- Shuffle-based 64-pt forward DFT over thread's 16 consecutive elements ----
__device__ __forceinline__ void fwd64_regs(float2 v[16], int t, float2 wr) {
    float f2 = (t & 2) ? -1.0f : 1.0f;
    float f1 = (t & 1) ? -1.0f : 1.0f;
    bool t3 = (t == 3);
    #pragma unroll
    for (int m = 0; m < 16; ++m) {
        float2 p = shxor(v[m], 2);
        v[m] = make_float2(f2 * v[m].x + p.x, f2 * v[m].y + p.y);
        if (t3) v[m] = mni(v[m]);
        p = shxor(v[m], 1);
        v[m] = make_float2(f1 * v[m].x + p.x, f1 * v[m].y + p.y);
    }
    twpow_mul(v, wr);     // w64^(r*m)
    dft16(v);
}

// ---- Shuffle-based 64-pt inverse ----
__device__ __forceinline__ void inv64_regs(float2 v[16], int t, float2 wrc) {
    float2 w2[16];
    #pragma unroll
    for (int k = 0; k < 16; ++k) w2[k] = v[OUTI(k)];   // natural freq order
    idft16(w2);                                         // time m at slot OUTI(m)
    #pragma unroll
    for (int m = 0; m < 16; ++m) v[m] = w2[OUTI(m)];    // natural time order
    twpow_mul(v, wrc);    // conj(w64)^(r*m)
    float f2 = (t & 2) ? -1.0f : 1.0f;
    float f1 = (t & 1) ? -1.0f : 1.0f;
    bool t3 = (t == 3);
    #pragma unroll
    for (int m = 0; m < 16; ++m) {
        float2 p = shxor(v[m], 1);
        v[m] = make_float2(f1 * v[m].x + p.x, f1 * v[m].y + p.y);
        if (t3) v[m] = mpi(v[m]);
        p = shxor(v[m], 2);
        v[m] = make_float2(f2 * v[m].x + p.x, f2 * v[m].y + p.y);
    }
}

// ---- conv middle: fwd64 + pointwise Kf + inv64 entirely in registers ----
__device__ __forceinline__ void conv_mid(float2* d, const float2* __restrict__ kf, int tid) {
    int t = tid & 3;
    int r = ((t & 1) << 1) | (t >> 1);
    float sn, cs;
    sincospif((float)r * (1.0f/32.0f), &sn, &cs);
    int base = tid << 4;
    float4* p4 = (float4*)(d + SK(base));
    float2 v[16];
    #pragma unroll
    for (int u = 0; u < 8; ++u) {
        float4 q = p4[u];
        v[2*u]   = make_float2(q.x, q.y);
        v[2*u+1] = make_float2(q.z, q.w);
    }
    fwd64_regs(v, t, make_float2(cs, -sn));
    const float4* k4 = (const float4*)(kf + (((tid >> 2) << 6) + (r << 4)));
    #pragma unroll
    for (int u = 0; u < 8; ++u) {
        float4 kk = k4[u];
        v[2*u]   = cmul(v[2*u],   make_float2(kk.x, kk.y));
        v[2*u+1] = cmul(v[2*u+1], make_float2(kk.z, kk.w));
    }
    inv64_regs(v, t, make_float2(cs, sn));
    #pragma unroll
    for (int u = 0; u < 8; ++u)
        p4[u] = make_float4(v[2*u].x, v[2*u].y, v[2*u+1].x, v[2*u+1].y);
}

// ---- kf middle: fwd64 in registers, store at permuted base (g, r, slot) ----
__device__ __forceinline__ void kf_mid(float2* d, int tid) {
    int t = tid & 3;
    int r = ((t & 1) << 1) | (t >> 1);
    float sn, cs;
    sincospif((float)r * (1.0f/32.0f), &sn, &cs);
    const float4* p4 = (const float4*)(d + SK(tid << 4));
    float2 v[16];
    #pragma unroll
    for (int u = 0; u < 8; ++u) {
        float4 q = p4[u];
        v[2*u]   = make_float2(q.x, q.y);
        v[2*u+1] = make_float2(q.z, q.w);
    }
    fwd64_regs(v, t, make_float2(cs, -sn));
    int sbase = ((tid >> 2) << 6) + (r << 4);
    float4* s4 = (float4*)(d + SK(sbase));
    #pragma unroll
    for (int u = 0; u < 8; ++u)
        s4[u] = make_float4(v[2*u].x, v[2*u].y, v[2*u+1].x, v[2*u+1].y);
}

// ---- Stage I3: inverse radix-16 q=1024, only outputs m<8, write gmem + bias ----
__device__ __forceinline__ void i3_store(const float2* d, const float2* tw,
                                         const float* __restrict__ x0,
                                         const float* __restrict__ x1,
                                         float* __restrict__ o0,
                                         float* __restrict__ o1,
                                         float bc, int tid) {
    int j = tid;
    float2 w = tw[j]; w.y = -w.y;
    float2 v[16];
    load_tw16(d, j, 10, v, w);
    idft16_cols_tw(v);
    #pragma unroll
    for (int r = 0; r < 4; ++r) {
        float2 a = v[4*r], b = v[4*r+1], c = v[4*r+2], e = v[4*r+3];
        float2 u0 = cadd(a,c), u1 = csub(a,c), u2 = cadd(b,e), u3 = csub(b,e);
        float2 y0 = cadd(u0,u2);
        float2 y1 = cadd(u1, mpi(u3));
        int i0 = j + (r << 10);
        int i1 = j + ((r + 4) << 10);
        o0[i0] = y0.x + x0[i0] * bc;  o1[i0] = y0.y + x1[i0] * bc;
        o0[i1] = y1.x + x0[i1] * bc;  o1[i1] = y1.y + x1[i1] * bc;
    }
}

// ---------------- Kernel 1: FUSED implicit MLP + projection + modulation ----------
// One block = 16 sequence positions (grid 512). Phase 1: block MLP. Phase 2:
// projection with SPILL-FREE accumulation: the ORD=64 dimension is processed in
// 4 quarters of 16 h-values, so live registers stay ~40 (round-14 bug: hreg[64]
// spilled to local memory, gating issue at 37.5%).
__global__ void __launch_bounds__(256) filt_kernel(const float* __restrict__ z,
                                                   const float* __restrict__ W0, const float* __restrict__ b0,
                                                   const float* __restrict__ W1, const float* __restrict__ b1,
                                                   const float* __restrict__ W2, const float* __restrict__ b2,
                                                   const float* __restrict__ freq,
                                                   const float* __restrict__ Wout,
                                                   const float* __restrict__ deltas) {
    extern __shared__ float fs[];
    float* sW0  = fs + FS_W0;     // [33*64]
    float* sW12 = fs + FS_W12;    // [8192] W1|W2, reused for Wout chunks in phase 2
    float* sz   = fs + FS_Z;      // [4][36]
    float* sh1  = fs + FS_H1;     // [4][68]
    float* sh2  = fs + FS_H2;     // [4][68]
    float* sH   = fs + FS_H;      // [16][68]

    int tid = threadIdx.x;
    int o = tid & 63;
    int p = tid >> 6;
    int lt = blockIdx.x * 16;

    for (int i = tid; i < EMB * ORD; i += 256) sW0[i] = W0[i];
    for (int i = tid; i < ORD * ORD; i += 256) sW12[i] = W1[i];
    for (int i = tid; i < ORD * ORD; i += 256) sW12[4096 + i] = W2[i];
    float fb0 = b0[o], fb1 = b1[o], fb2 = b2[o], fq = freq[o];
    __syncthreads();

    // ---- Phase 1: MLP for 16 positions (4 iterations x 4 positions) ----
    for (int it = 0; it < 4; ++it) {
        int l = lt + it * 4 + p;
        if (o < EMB) sz[p * 36 + o] = z[l * EMB + o];
        __syncthreads();
        float acc = fb0;
        #pragma unroll
        for (int e = 0; e < EMB; ++e) acc += sz[p * 36 + e] * sW0[e * ORD + o];
        sh1[p * 68 + o] = sinf(fq * acc);
        __syncthreads();
        acc = fb1;
        #pragma unroll 8
        for (int i = 0; i < ORD; ++i) acc += sh1[p * 68 + i] * sW12[i * ORD + o];
        sh2[p * 68 + o] = sinf(fq * acc);
        __syncthreads();
        acc = fb2;
        #pragma unroll 8
        for (int i = 0; i < ORD; ++i) acc += sh2[p * 68 + i] * sW12[4096 + i * ORD + o];
        sH[(it * 4 + p) * 68 + o] = sinf(fq * acc);
        __syncthreads();
    }

    // ---- Phase 2: projection to 768 channels + exponential modulation ----
    int ll = tid & 15;            // position within tile
    int cs = tid >> 4;            // 0..15, owns 8 consecutive channels per chunk
    float tl = (float)(lt + ll) * (1.0f / (float)(LL - 1));
    float4* sW4 = (float4*)sW12;   // reuse weight region for Wout chunk [64][128]
    const float4* hrow = (const float4*)(sH + ll * 68);

    for (int ch = 0; ch < 6; ++ch) {
        int c0 = ch * 128;
        __syncthreads();
        for (int idx = tid; idx < ORD * 128; idx += 256) {
            int oo = idx >> 7, cc = idx & 127;
            sW12[oo * 128 + cc] = Wout[oo * CC + c0 + cc];
        }
        __syncthreads();

        float acc[8];
        #pragma unroll
        for (int j = 0; j < 8; ++j) acc[j] = 0.0f;
        // process ORD in 4 quarters of 16 h-values -> no register spill
        #pragma unroll
        for (int q = 0; q < 4; ++q) {
            float hq[16];
            #pragma unroll
            for (int i = 0; i < 4; ++i) {
                float4 t = hrow[q * 4 + i];
                hq[4*i] = t.x; hq[4*i+1] = t.y; hq[4*i+2] = t.z; hq[4*i+3] = t.w;
            }
            #pragma unroll
            for (int oi = 0; oi < 16; ++oi) {
                float h = hq[oi];
                const float4* row = sW4 + (q * 16 + oi) * 32 + cs * 2;
                float4 w0 = row[0], w1 = row[1];
                acc[0] += h * w0.x;  acc[1] += h * w0.y;
                acc[2] += h * w0.z;  acc[3] += h * w0.w;
                acc[4] += h * w1.x;  acc[5] += h * w1.y;
                acc[6] += h * w1.z;  acc[7] += h * w1.w;
            }
        }
        #pragma unroll
        for (int j = 0; j < 8; ++j) {
            int c = c0 + cs * 8 + j;
            float m = expf(-tl * fabsf(deltas[c]));
            g_k[c * LL + lt + ll] = acc[j] * m;
        }
    }
}

// ---------------- Kernel 2: filter spectra, two channels per FFT ------------------
// Output layout per channel: p = 64g + 16r + u (u = dft16 slot; freq s = OUTI(u)).
__global__ void __launch_bounds__(NT, 1) kf_fft_kernel() {
    extern __shared__ float2 sm[];
    float2* data = sm;
    float2* tw   = sm + DATA_SZ;
    int tid = threadIdx.x;
    int c0  = blockIdx.x * 2;
    int c1  = c0 + 1;

    fill_tw(tw, tid);
    f0_fwd(data, tw, g_k + (size_t)c0 * LL, g_k + (size_t)c1 * LL, tid);
    r16_fwd64(data, tw, tid);
    bar128(tid);
    kf_mid(data, tid);
    __syncthreads();

    const float s = 0.5f / (float)NFFT;
    float2* KF0 = g_KF + (size_t)c0 * NFFT;
    float2* KF1 = g_KF + (size_t)c1 * NFFT;
    for (int p = tid; p < NFFT; p += NT) {
        int g = p >> 6, rr = (p >> 4) & 3, u = p & 15;
        int ss = OUTI(u);
        int j  = (g >> 4) + ((g & 15) << 4) + (((ss << 2) | rr) << 8);
        int jn = (NFFT - j) & (NFFT - 1);
        int a2 = jn & 15, b2 = (jn >> 4) & 15, k2 = jn >> 8;
        int r2 = k2 & 3, s2 = k2 >> 2;
        int u2 = OUTI(s2);
        int p2 = (((a2 << 4) | b2) << 6) | (r2 << 4) | u2;
        float2 z1 = data[SK(p)];
        float2 z2 = data[SK(p2)];
        KF0[p] = make_float2(s * (z1.x + z2.x), s * (z1.y - z2.y));
        KF1[p] = make_float2(s * (z1.y + z2.y), s * (z2.x - z1.x));
    }
}

// ---------------- Kernel 3: batched FFT convolution (2 batches as one complex) ----
__global__ void __launch_bounds__(NT, 1) conv_fft_kernel(const float* __restrict__ x,
                                                         const float* __restrict__ bias,
                                                         float* __restrict__ out) {
    extern __shared__ float2 sm[];
    float2* data = sm;
    float2* tw   = sm + DATA_SZ;
    int tid = threadIdx.x;
    int c = blockIdx.x;
    int p = blockIdx.y;

    const float* x0 = x + ((size_t)(2*p)   * CC + c) * LL;
    const float* x1 = x + ((size_t)(2*p+1) * CC + c) * LL;

    fill_tw(tw, tid);
    f0_fwd(data, tw, x0, x1, tid);          // block barrier inside

    r16_fwd64(data, tw, tid);
    bar128(tid);                            // 64-block exchange within tid>>6 group

    conv_mid(data, g_KF + (size_t)c * NFFT, tid);
    bar128(tid);

    r16_inv64(data, tw, tid);
    __syncthreads();                        // i3 reads across all threads

    float bc = bias[c];
    float* o0 = out + ((size_t)(2*p)   * CC + c) * LL;
    float* o1 = out + ((size_t)(2*p+1) * CC + c) * LL;
    i3_store(data, tw, x0, x1, o0, o1, bc, tid);
}

extern "C" void kernel_launch(void* const* d_in, const int* in_sizes, int n_in,
                              void* d_out, int out_size) {
    const float* x      = (const float*)d_in[0];
    const float* bias   = (const float*)d_in[1];
    const float* z      = (const float*)d_in[2];
    const float* deltas = (const float*)d_in[3];
    const float* W0     = (const float*)d_in[4];
    const float* b0     = (const float*)d_in[5];
    const float* W1     = (const float*)d_in[6];
    const float* b1     = (const float*)d_in[7];
    const float* W2     = (const float*)d_in[8];
    const float* b2     = (const float*)d_in[9];
    const float* freq   = (const float*)d_in[10];
    const float* Wout   = (const float*)d_in[11];
    float* out = (float*)d_out;

    cudaFuncSetAttribute(filt_kernel,     cudaFuncAttributeMaxDynamicSharedMemorySize, FILT_SMEM);
    cudaFuncSetAttribute(kf_fft_kernel,   cudaFuncAttributeMaxDynamicSharedMemorySize, FFT_SMEM);
    cudaFuncSetAttribute(conv_fft_kernel, cudaFuncAttributeMaxDynamicSharedMemorySize, FFT_SMEM);

    filt_kernel<<<LL / 16, 256, FILT_SMEM>>>(z, W0, b0, W1, b1, W2, b2, freq, Wout, deltas);
    kf_fft_kernel<<<CC / 2, NT, FFT_SMEM>>>();
    conv_fft_kernel<<<dim3(CC, BB / 2), NT, FFT_SMEM>>>(x, bias, out);
}